// round 11
// baseline (speedup 1.0000x reference)
#include <cuda_runtime.h>

// DTW 65536 x 512 — 4 CTAs x 128 threads, 1 column/lane, R=32 rows/tick.
// R11 = R10 with the per-iteration __syncthreads relaxed to every 2nd
// iteration. Inter-warp skew deepened 32 -> 34 ticks so the edgebuf
// consumer reads data 3 iterations old (>=1 barrier epoch between write
// and read, >=2 epochs before overwrite at depth 8). Warp-private x-ring
// refill gains a __syncwarp (was ordered by the removed barrier).
// #pragma unroll 2 lets ptxas overlap iter i+1's independent front-end
// (LDS x, residuals) with iter i's serial chain.

#define N_ROWS  65536
#define NCTA    4
#define NTHR    128
#define NWARP   4
#define R       32
#define NTICK   (N_ROWS / R)          // 2048
#define WSKEW   34                    // ticks of skew per warp
#define MAXSKW  (WSKEW * (NWARP - 1) + 31)   // 133
#define NITER   (NTICK + MAXSKW + 1)  // 2182 (even)
#define CHUNK   32                    // ticks per cross-CTA chunk
#define XSTRIDE 36                    // floats per ring slot (32 data + 4 pad)
#define EBD     8                     // edgebuf depth

__device__ __align__(16) float g_edge[NCTA - 1][N_ROWS];
__device__ int g_flag[NCTA - 1];

__global__ void dtw_init_flags()
{
    if (threadIdx.x < NCTA - 1) g_flag[threadIdx.x] = 0;
}

__device__ __forceinline__ int flag_acquire(const int* p)
{
    int v;
    asm volatile("ld.acquire.gpu.global.b32 %0, [%1];" : "=r"(v) : "l"(p) : "memory");
    return v;
}

__device__ __forceinline__ void flag_release(int* p, int v)
{
    asm volatile("st.release.gpu.global.b32 [%0], %1;" :: "l"(p), "r"(v) : "memory");
}

__global__ __launch_bounds__(NTHR, 1)
void dtw_relax_kernel(const float* __restrict__ x,
                      const float* __restrict__ kern,
                      float* __restrict__ out)
{
    __shared__ __align__(16) float  s_xring[NWARP][64 * XSTRIDE]; // 36 KB x rings
    __shared__ __align__(16) float  lbuf[2][CHUNK * R];           // 8 KB cross-CTA staging
    __shared__ __align__(16) float4 edgebuf[EBD][NWARP][8];       // 4 KB intra-CTA handoff

    const int   c   = (int)blockIdx.x;
    const int   tid = (int)threadIdx.x;
    const int   w   = tid >> 5;
    const int   l   = tid & 31;
    const int   skw = WSKEW * w + l;
    const float INF = __int_as_float(0x7f800000);

    const float kv    = kern[c * NTHR + tid];
    const bool  pred0 = (c == 0) && (tid == 0);
    float* const myring = s_xring[w];

    // ---- initial x ring fill: ticks [-34w-31, -34w+32], 2 slots per lane ----
    #pragma unroll
    for (int k2 = 0; k2 < 2; ++k2) {
        const int T  = -WSKEW * w - 31 + l + 32 * k2;
        const int Tc = min(max(T, 0), NTICK - 1);
        const float4* xp = (const float4*)(x + Tc * R);
        float4* dst = (float4*)&myring[(((unsigned)T) & 63u) * XSTRIDE];
        #pragma unroll
        for (int q = 0; q < 8; ++q) dst[q] = xp[q];
    }

    // ---- prestage chunk 0 of the left-CTA boundary ----
    if (c == 0) {
        #pragma unroll
        for (int k = 0; k < (2 * CHUNK * R) / NTHR; ++k)
            lbuf[0][tid + NTHR * k] = INF;
    } else {
        if (tid == 0) {
            while (flag_acquire(&g_flag[c - 1]) < CHUNK) { }
        }
        __syncthreads();
        #pragma unroll
        for (int k2 = 0; k2 < 2; ++k2)
            *(float4*)&lbuf[0][4 * (2 * tid + k2)] =
                __ldcg((const float4*)g_edge[c - 1] + 2 * tid + k2);
    }
    __syncthreads();

    float ev[R];
    #pragma unroll
    for (int r = 0; r < R; ++r) ev[r] = INF;
    float vprev = INF, dlast = INF;

    #pragma unroll 2
    for (int i = 0; i < NITER; ++i) {
        // ---- left-neighbor values (previous iteration's ev of lane l-1) ----
        float L[R];
        #pragma unroll
        for (int r = 0; r < R; ++r)
            L[r] = __shfl_up_sync(0xffffffffu, ev[r], 1);

        // ---- every 32 iters: refill my ring + cross-CTA chunk staging ----
        if ((i & (CHUNK - 1)) == 0) {
            {
                const int T  = i - WSKEW * w + l;
                const int Tc = min(max(T, 0), NTICK - 1);
                const float4* xp = (const float4*)(x + Tc * R);
                float4* dst = (float4*)&myring[(((unsigned)T) & 63u) * XSTRIDE];
                #pragma unroll
                for (int q = 0; q < 8; ++q) dst[q] = xp[q];
            }
            if (c > 0) {
                const int base = i + CHUNK;
                if (base < NTICK) {
                    if (tid == 0) {
                        const int need = min(base + CHUNK, NTICK);
                        while (flag_acquire(&g_flag[c - 1]) < need) { }
                    }
                    __syncthreads();
                    const int buf = ((i >> 5) + 1) & 1;
                    #pragma unroll
                    for (int k2 = 0; k2 < 2; ++k2)
                        *(float4*)&lbuf[buf][4 * (2 * tid + k2)] =
                            __ldcg((const float4*)(g_edge[c - 1] + base * R) + 2 * tid + k2);
                }
            }
            __syncwarp();   // order ring STS before warp-mates' LDS (no per-iter bar now)
        }

        // ---- lane-0 boundary source (warp-uniform branch, broadcast LDS) ----
        {
            float4 eb4[8];
            if (w == 0) {
                const float4* lb = (const float4*)&lbuf[(i >> 5) & 1][(i & (CHUNK - 1)) * R];
                #pragma unroll
                for (int q = 0; q < 8; ++q) eb4[q] = lb[q];
            } else {
                // written by warp w-1 at iteration i-3 (skew gap = 34-31 = 3)
                const float4* eb = (const float4*)edgebuf[(i - 3) & (EBD - 1)][w - 1];
                #pragma unroll
                for (int q = 0; q < 8; ++q) eb4[q] = eb[q];
            }
            const float* Lb = (const float*)eb4;
            #pragma unroll
            for (int r = 0; r < R; ++r)
                L[r] = (l == 0) ? Lb[r] : L[r];
        }
        // virtual 0 at (row 0, col -1): left-use only, at cell (0,0)
        L[0] = (pred0 && i == 0) ? 0.0f : L[0];

        const int  t      = i - skw;
        const bool active = (t >= 0) && (t < NTICK);

        // ---- m = min(diag, left), in place (descending keeps deps correct) ----
        const float lastL = L[R - 1];
        #pragma unroll
        for (int r = R - 1; r >= 1; --r)
            L[r] = fminf(L[r - 1], L[r]);
        L[0] = fminf(dlast, L[0]);

        // ---- x residuals (parallel, off-chain) ----
        float ts[R];
        {
            const float* sp = &myring[(((unsigned)t) & 63u) * XSTRIDE];
            #pragma unroll
            for (int h = 0; h < 8; ++h) {
                const float4 a = ((const float4*)sp)[h];
                ts[4*h]   = kv - a.x;
                ts[4*h+1] = kv - a.y;
                ts[4*h+2] = kv - a.z;
                ts[4*h+3] = kv - a.w;
            }
        }

        // ---- min-plus prefix: two concurrent 4-cyc chains ----
        float S  = ts[0] * ts[0];
        float cm = fminf(vprev, L[0]);
        ev[0] = S + cm;
        #pragma unroll
        for (int r = 1; r < R; ++r) {
            const float q = L[r] - S;           // m[r] - S[r-1]
            S  = fmaf(ts[r], ts[r], S);         // S[r]
            cm = fminf(cm, q);                  // cm[r]
            ev[r] = S + cm;                     // unconditional commit
        }
        vprev = active ? ev[R - 1] : vprev;
        dlast = active ? lastL : dlast;

        // ---- publish right edge ----
        if (l == 31 && active) {
            float4 o4[8];
            #pragma unroll
            for (int q = 0; q < 8; ++q)
                o4[q] = make_float4(ev[4*q], ev[4*q+1], ev[4*q+2], ev[4*q+3]);
            if (w < NWARP - 1) {
                float4* eb = edgebuf[i & (EBD - 1)][w];
                #pragma unroll
                for (int q = 0; q < 8; ++q) eb[q] = o4[q];
            } else if (c < NCTA - 1) {
                float4* ep = (float4*)(g_edge[c] + t * R);
                #pragma unroll
                for (int q = 0; q < 8; ++q) ep[q] = o4[q];
                if ((t & 7) == 7)
                    flag_release(&g_flag[c], t + 1);
            } else {
                float4* op = (float4*)(out + t * R);
                #pragma unroll
                for (int q = 0; q < 8; ++q) op[q] = o4[q];
            }
        }

        // ---- barrier every 2nd iteration (epochs of 2) ----
        if (i & 1) __syncthreads();
    }
}

extern "C" void kernel_launch(void* const* d_in, const int* in_sizes, int n_in,
                              void* d_out, int out_size)
{
    const float* x = (const float*)d_in[0];   // input  [65536]
    const float* k = (const float*)d_in[1];   // kernel [512]
    float* out = (float*)d_out;               // [65536] float32

    dtw_init_flags<<<1, 32>>>();
    dtw_relax_kernel<<<NCTA, NTHR>>>(x, k, out);
}